// round 11
// baseline (speedup 1.0000x reference)
#include <cuda_runtime.h>
#include <math.h>

#define BB 32
#define NN 300
#define TT 12
#define DD 64
#define MM 16
#define BT (BB*TT)        // 384
#define ND (NN*DD)        // 19200
#define NN2 (NN*NN)       // 90000

// ---- scratch (device globals; no runtime allocation) ----
__device__ float2 g_SB[NN2];           // (alpha1@alpha2, beta1@beta2) interleaved
__device__ float g_W[NN*DD*DD];        // per-node weights [N,64,64]
__device__ float g_gcnWT4[192*DD];     // gcnW rearranged
__device__ float g_A[(size_t)BT*NN2];  // adjacency per (b,t)   ~138MB
__device__ float g_Xp[(size_t)BT*ND];  // X transposed [bt][n][d]
__device__ float g_H1[(size_t)BT*ND];
__device__ float g_H2[(size_t)BT*ND];
__device__ float g_Tmp[(size_t)BT*ND];

// ---- packed fp32x2 helpers (SASS FFMA2 path) ----
typedef unsigned long long u64;
__device__ __forceinline__ void fma2(u64 &d, u64 a, u64 b) {
    asm("fma.rn.f32x2 %0, %1, %2, %3;" : "=l"(d) : "l"(a), "l"(b), "l"(d));
}
__device__ __forceinline__ u64 rep2(float x) {
    u64 r; unsigned int u = __float_as_uint(x);
    asm("mov.b64 %0, {%1,%1};" : "=l"(r) : "r"(u));
    return r;
}
__device__ __forceinline__ float lo2(u64 v) { return __uint_as_float((unsigned)v); }
__device__ __forceinline__ float hi2(u64 v) { return __uint_as_float((unsigned)(v >> 32)); }

// gated residual: sigmoid(x)*tanh(x) == (1-e^-x)/(1+e^-2x)
__device__ __forceinline__ float gated(float p) {
    float pc = fminf(fmaxf(p, -20.f), 20.f);
    float u = __expf(-pc);
    return __fdividef(1.f - u, 1.f + u*u);
}

// 8x8 micro-tile kernel step with minimal live B registers
__device__ __forceinline__ void micro_step(u64 (&acc)[4][8], const u64 (&ap)[4],
                                           const float4 &b0, const float4 &b1) {
    const float bv[8] = {b0.x,b0.y,b0.z,b0.w,b1.x,b1.y,b1.z,b1.w};
#pragma unroll
    for (int j = 0; j < 8; j++) {
        u64 brj = rep2(bv[j]);
#pragma unroll
        for (int i = 0; i < 4; i++)
            fma2(acc[i][j], ap[i], brj);
    }
}

// ---------------- tiny precompute kernels ----------------
__global__ void k_SB(const float* __restrict__ a1, const float* __restrict__ a2,
                     const float* __restrict__ b1, const float* __restrict__ b2) {
    int idx = blockIdx.x*256 + threadIdx.x;
    if (idx >= NN2) return;
    int i = idx / NN, k = idx % NN;
    float s = 0.f, bm = 0.f;
#pragma unroll
    for (int m = 0; m < MM; m++) {
        s  += a1[i*MM+m] * a2[m*NN+k];
        bm += b1[i*MM+m] * b2[m*NN+k];
    }
    g_SB[idx] = make_float2(s, bm);
}

__global__ void k_Wp(const float* __restrict__ w1, const float* __restrict__ w2) {
    int idx = blockIdx.x*256 + threadIdx.x;
    if (idx >= NN*DD*DD) return;
    int n = idx / (DD*DD), r = idx % (DD*DD);
    float s = 0.f;
#pragma unroll
    for (int m = 0; m < MM; m++) s += w1[n*MM+m] * w2[m*DD*DD+r];
    g_W[idx] = s;
}

__global__ void k_gWT(const float* __restrict__ gcnW) {
    int idx = blockIdx.x*256 + threadIdx.x;
    if (idx >= 192*DD) return;
    int i  = idx & 3;
    int d  = (idx >> 2) & 63;
    int f4 = idx >> 8;
    g_gcnWT4[idx] = gcnW[d*192 + f4*4 + i];
}

// transpose X[b,d,n,t] -> Xp[bt][n][d]
__global__ void k_txp(const float* __restrict__ X) {
    int n = blockIdx.x, b = blockIdx.y;
    __shared__ float tile[DD][13];
    int tid = threadIdx.x;
#pragma unroll
    for (int i = 0; i < 3; i++) {
        int lin = tid + i*256;
        if (lin < DD*TT) {
            int d = lin / TT, t = lin % TT;
            tile[d][t] = X[(((size_t)b*DD+d)*NN+n)*TT + t];
        }
    }
    __syncthreads();
#pragma unroll
    for (int i = 0; i < 3; i++) {
        int lin = tid + i*256;
        if (lin < DD*TT) {
            int t = lin >> 6, d = lin & 63;
            g_Xp[(size_t)(b*TT+t)*ND + n*DD + d] = tile[d][t];
        }
    }
}

// ---------------- adjacency: A = relu(S * sin(te@adjW^T + adjB) + Bm) ----------------
__global__ void __launch_bounds__(128, 6) k_adj(const float* __restrict__ te,
                                                const float* __restrict__ adjW,
                                                const float* __restrict__ adjB) {
    const int bt = blockIdx.y;
    const int b = bt / TT, t = bt % TT;
    const int rt = blockIdx.x % 3;
    const int ct = blockIdx.x / 3;
    const int rowBase = rt*128, colBase = ct*64;
    __shared__ __align__(16) float As_t[32][132];
    __shared__ __align__(16) float Bs[32][68];
    const int tid = threadIdx.x;
    const int tx = tid & 7;
    const int ty = tid >> 3;
    u64 acc[4][8] = {};

    for (int k0 = 0; k0 < DD; k0 += 32) {
        {
            int row = rowBase + tid;
            const float* src = te + (((size_t)b*NN + row)*TT + t)*DD + k0;
#pragma unroll
            for (int c = 0; c < 8; c++) {
                float4 v = (row < NN) ? *(const float4*)(src + 4*c)
                                      : make_float4(0.f,0.f,0.f,0.f);
                As_t[4*c+0][tid] = v.x; As_t[4*c+1][tid] = v.y;
                As_t[4*c+2][tid] = v.z; As_t[4*c+3][tid] = v.w;
            }
        }
#pragma unroll
        for (int i = 0; i < 4; i++) {
            int lin = tid + i*128;
            int col = lin >> 3, kc = lin & 7;
            int gcol = colBase + col;
            float4 v = (gcol < NN) ? *(const float4*)(adjW + gcol*DD + k0 + kc*4)
                                   : make_float4(0.f,0.f,0.f,0.f);
            Bs[kc*4+0][col] = v.x; Bs[kc*4+1][col] = v.y;
            Bs[kc*4+2][col] = v.z; Bs[kc*4+3][col] = v.w;
        }
        __syncthreads();
#pragma unroll 8
        for (int kk = 0; kk < 32; kk++) {
            ulonglong2 ap0 = *(const ulonglong2*)&As_t[kk][ty*8];
            ulonglong2 ap1 = *(const ulonglong2*)&As_t[kk][ty*8+4];
            float4 b0 = *(const float4*)&Bs[kk][tx*8];
            float4 b1 = *(const float4*)&Bs[kk][tx*8+4];
            u64 ap[4] = {ap0.x, ap0.y, ap1.x, ap1.y};
            micro_step(acc, ap, b0, b1);
        }
        __syncthreads();
    }

    // epilogue: sin / scale / relu (MUFU.SIN), S/Bm fused as float2
    float* Aout = g_A + (size_t)bt*NN2;
    const int c0 = colBase + tx*8;
#pragma unroll
    for (int i = 0; i < 4; i++) {
        int r0 = rowBase + ty*8 + 2*i;
#pragma unroll
        for (int lane = 0; lane < 2; lane++) {
            int row = r0 + lane;
            if (row >= NN) continue;
            const float2* sb = g_SB + (size_t)row*NN + c0;
#pragma unroll
            for (int j = 0; j < 8; j++) {
                int col = c0 + j;
                if (col >= NN) continue;
                float pre = lane ? hi2(acc[i][j]) : lo2(acc[i][j]);
                float v = __sinf(pre + adjB[col]);
                float2 s = sb[j];
                v = s.x*v + s.y;
                Aout[(size_t)row*NN + col] = v > 0.f ? v : 0.f;
            }
        }
    }
}

// ---------------- Tmp = A @ Hb  (per bt: [300,300]@[300,64]) ----------------
__global__ void __launch_bounds__(128, 6) k_mm(int hop) {
    const int bt = blockIdx.y;
    const int rowBase = blockIdx.x*128;
    const float* Hb = (hop == 0) ? g_Xp : g_H1;
    const float* Abt = g_A + (size_t)bt*NN2;
    const float* Hbt = Hb + (size_t)bt*ND;
    __shared__ __align__(16) float As_t[32][132];
    __shared__ __align__(16) float Bs[32][68];
    const int tid = threadIdx.x;
    const int tx = tid & 7;
    const int ty = tid >> 3;
    u64 acc[4][8] = {};

    for (int k0 = 0; k0 < 320; k0 += 32) {
        {
            int row = rowBase + tid;
            const float* src = Abt + (size_t)row*NN + k0;
#pragma unroll
            for (int c = 0; c < 8; c++) {
                float4 v;
                if (row < NN && (k0 + 4*c + 3) < NN) v = *(const float4*)(src + 4*c);
                else v = make_float4(0.f,0.f,0.f,0.f);
                As_t[4*c+0][tid] = v.x; As_t[4*c+1][tid] = v.y;
                As_t[4*c+2][tid] = v.z; As_t[4*c+3][tid] = v.w;
            }
        }
#pragma unroll
        for (int i = 0; i < 4; i++) {
            int lin = tid + i*128;
            int kk = lin >> 4, d4 = lin & 15;
            int k = k0 + kk;
            float4 v = (k < NN) ? *(const float4*)(Hbt + (size_t)k*DD + d4*4)
                                : make_float4(0.f,0.f,0.f,0.f);
            *(float4*)&Bs[kk][d4*4] = v;
        }
        __syncthreads();
#pragma unroll 8
        for (int kk = 0; kk < 32; kk++) {
            ulonglong2 ap0 = *(const ulonglong2*)&As_t[kk][ty*8];
            ulonglong2 ap1 = *(const ulonglong2*)&As_t[kk][ty*8+4];
            float4 b0 = *(const float4*)&Bs[kk][tx*8];
            float4 b1 = *(const float4*)&Bs[kk][tx*8+4];
            u64 ap[4] = {ap0.x, ap0.y, ap1.x, ap1.y};
            micro_step(acc, ap, b0, b1);
        }
        __syncthreads();
    }

    float* Tbt = g_Tmp + (size_t)bt*ND;
    const int c0 = tx*8;
#pragma unroll
    for (int i = 0; i < 4; i++) {
        int r0 = rowBase + ty*8 + 2*i;
        if (r0 < NN) {
            *(float4*)&Tbt[(size_t)r0*DD + c0] =
                make_float4(lo2(acc[i][0]), lo2(acc[i][1]), lo2(acc[i][2]), lo2(acc[i][3]));
            *(float4*)&Tbt[(size_t)r0*DD + c0 + 4] =
                make_float4(lo2(acc[i][4]), lo2(acc[i][5]), lo2(acc[i][6]), lo2(acc[i][7]));
        }
        if (r0 + 1 < NN) {
            *(float4*)&Tbt[(size_t)(r0+1)*DD + c0] =
                make_float4(hi2(acc[i][0]), hi2(acc[i][1]), hi2(acc[i][2]), hi2(acc[i][3]));
            *(float4*)&Tbt[(size_t)(r0+1)*DD + c0 + 4] =
                make_float4(hi2(acc[i][4]), hi2(acc[i][5]), hi2(acc[i][6]), hi2(acc[i][7]));
        }
    }
}

// ---------------- per-node matmul + gated residual (FFMA2) ----------------
__global__ void __launch_bounds__(128, 6) k_nodemm(int hop) {
    const int n = blockIdx.y;
    const int rowBase = blockIdx.x*128;
    float* Hout = (hop == 0) ? g_H1 : g_H2;
    const float* Wn = g_W + (size_t)n*DD*DD;
    __shared__ __align__(16) float As_t[32][132];
    __shared__ __align__(16) float Bs[32][68];
    const int tid = threadIdx.x;
    const int tx = tid & 7;
    const int ty = tid >> 3;
    u64 acc[4][8] = {};

    for (int k0 = 0; k0 < DD; k0 += 32) {
        {
            const float* src = g_Tmp + (size_t)(rowBase + tid)*ND + n*DD + k0;
#pragma unroll
            for (int c = 0; c < 8; c++) {
                float4 v = *(const float4*)(src + 4*c);
                As_t[4*c+0][tid] = v.x; As_t[4*c+1][tid] = v.y;
                As_t[4*c+2][tid] = v.z; As_t[4*c+3][tid] = v.w;
            }
        }
#pragma unroll
        for (int i = 0; i < 4; i++) {
            int lin = tid + i*128;
            int kk = lin >> 4, d4 = lin & 15;
            *(float4*)&Bs[kk][d4*4] = *(const float4*)(Wn + (size_t)(k0+kk)*DD + d4*4);
        }
        __syncthreads();
#pragma unroll 8
        for (int kk = 0; kk < 32; kk++) {
            ulonglong2 ap0 = *(const ulonglong2*)&As_t[kk][ty*8];
            ulonglong2 ap1 = *(const ulonglong2*)&As_t[kk][ty*8+4];
            float4 b0 = *(const float4*)&Bs[kk][tx*8];
            float4 b1 = *(const float4*)&Bs[kk][tx*8+4];
            u64 ap[4] = {ap0.x, ap0.y, ap1.x, ap1.y};
            micro_step(acc, ap, b0, b1);
        }
        __syncthreads();
    }

    const int c0 = tx*8;
#pragma unroll
    for (int i = 0; i < 4; i++) {
        int r0 = rowBase + ty*8 + 2*i;
#pragma unroll
        for (int lane = 0; lane < 2; lane++) {
            int bt = r0 + lane;
            size_t base = (size_t)bt*ND + n*DD + c0;
            float4 x0 = *(const float4*)(g_Xp + base);
            float4 x1 = *(const float4*)(g_Xp + base + 4);
            float v[8];
#pragma unroll
            for (int j = 0; j < 8; j++)
                v[j] = lane ? hi2(acc[i][j]) : lo2(acc[i][j]);
            float4 o0, o1;
            o0.x = gated(x0.x + v[0]); o0.y = gated(x0.y + v[1]);
            o0.z = gated(x0.z + v[2]); o0.w = gated(x0.w + v[3]);
            o1.x = gated(x1.x + v[4]); o1.y = gated(x1.y + v[5]);
            o1.z = gated(x1.z + v[6]); o1.w = gated(x1.w + v[7]);
            *(float4*)(Hout + base) = o0;
            *(float4*)(Hout + base + 4) = o1;
        }
    }
}

// ---------------- output: [Xp|H1|H2] @ gcnW^T + gcnB -> [B,D,N,T] ----------------
__global__ void __launch_bounds__(128) k_out(const float* __restrict__ gcnB,
                                             float* __restrict__ out) {
    const int b = blockIdx.y;
    const int nBase = blockIdx.x*4;
    __shared__ __align__(16) float Hc[4*12*192];
    const int tid = threadIdx.x;
    float4* Hc4 = (float4*)Hc;
#pragma unroll
    for (int i = 0; i < 18; i++) {
        int lin4 = tid + i*128;
        int nl = lin4 / 576;
        int rem = lin4 - nl*576;
        int t = rem / 48;
        int f4 = rem - t*48;
        int seg = f4 >> 4, fd4 = f4 & 15;
        const float* src = (seg == 0) ? g_Xp : ((seg == 1) ? g_H1 : g_H2);
        Hc4[lin4] = *(const float4*)(src + (size_t)(b*TT+t)*ND + (nBase+nl)*DD + fd4*4);
    }
    __syncthreads();
    const int d2 = tid & 31, nloc = tid >> 5;
    u64 acc[12][2] = {};
    const ulonglong2* WT = (const ulonglong2*)g_gcnWT4;
#pragma unroll 4
    for (int f4 = 0; f4 < 48; f4++) {
        ulonglong2 wA = WT[f4*64 + d2];
        ulonglong2 wB = WT[f4*64 + d2 + 32];
        const float* hb = &Hc[nloc*2304 + f4*4];
#pragma unroll
        for (int t = 0; t < 12; t++) {
            ulonglong2 hp = *(const ulonglong2*)&hb[t*192];
            fma2(acc[t][0], hp.x, wA.x);
            fma2(acc[t][0], hp.y, wA.y);
            fma2(acc[t][1], hp.x, wB.x);
            fma2(acc[t][1], hp.y, wB.y);
        }
    }
    const int n = nBase + nloc;
#pragma unroll
    for (int dsel = 0; dsel < 2; dsel++) {
        int d = d2 + dsel*32;
        float bias = gcnB[d];
        float* op = out + ((size_t)(b*DD+d)*NN + n)*TT;
        float v[12];
#pragma unroll
        for (int t = 0; t < 12; t++) v[t] = lo2(acc[t][dsel]) + hi2(acc[t][dsel]) + bias;
#pragma unroll
        for (int q = 0; q < 3; q++)
            *(float4*)&op[q*4] = make_float4(v[q*4], v[q*4+1], v[q*4+2], v[q*4+3]);
    }
}

// ---------------- launcher (k_adj stays in the ncu capture slot #4) --------
extern "C" void kernel_launch(void* const* d_in, const int* in_sizes, int n_in,
                              void* d_out, int out_size) {
    const float* X    = (const float*)d_in[0];
    const float* te   = (const float*)d_in[1];
    const float* adjW = (const float*)d_in[2];
    const float* adjB = (const float*)d_in[3];
    const float* tW1  = (const float*)d_in[4];
    const float* tW2  = (const float*)d_in[5];
    const float* a1   = (const float*)d_in[6];
    const float* a2   = (const float*)d_in[7];
    const float* b1   = (const float*)d_in[8];
    const float* b2   = (const float*)d_in[9];
    const float* gcnW = (const float*)d_in[10];
    const float* gcnB = (const float*)d_in[11];
    float* out = (float*)d_out;

    k_SB <<<(NN2 + 255)/256, 256>>>(a1, a2, b1, b2);          // 1
    k_txp<<<dim3(NN, BB), 256>>>(X);                          // 2
    k_Wp <<<(NN*DD*DD + 255)/256, 256>>>(tW1, tW2);           // 3
    k_adj<<<dim3(15, BT), 128>>>(te, adjW, adjB);             // 4  <- capture slot

    // hop 1
    k_mm    <<<dim3(3, BT), 128>>>(0);                        // 5
    k_nodemm<<<dim3(3, NN), 128>>>(0);                        // 6
    // hop 2
    k_mm    <<<dim3(3, BT), 128>>>(1);                        // 7
    k_nodemm<<<dim3(3, NN), 128>>>(1);                        // 8

    k_gWT<<<(192*DD + 255)/256, 256>>>(gcnW);                 // 9
    k_out<<<dim3(75, BB), 128>>>(gcnB, out);                  // 10
}

// round 12
// speedup vs baseline: 1.5876x; 1.5876x over previous
#include <cuda_runtime.h>
#include <math.h>

#define BB 32
#define NN 300
#define TT 12
#define DD 64
#define MM 16
#define BT (BB*TT)        // 384
#define ND (NN*DD)        // 19200
#define NN2 (NN*NN)       // 90000
#define MFLAT (BT*NN)     // 115200 = 900 * 128

// ---- scratch (device globals; no runtime allocation) ----
__device__ float g_S[NN2];             // alpha1@alpha2
__device__ float g_Bm[NN2];            // beta1@beta2
__device__ float g_W[NN*DD*DD];        // per-node weights [N,64,64]
__device__ float g_gcnWT4[192*DD];     // gcnW rearranged
__device__ float g_A[(size_t)BT*NN2];  // adjacency per (b,t)   ~138MB
__device__ float g_Xp[(size_t)BT*ND];  // X transposed [bt][n][d]
__device__ float g_H1[(size_t)BT*ND];
__device__ float g_H2[(size_t)BT*ND];
__device__ float g_Tmp[(size_t)BT*ND];

// ---- packed fp32x2 helpers (SASS FFMA2 path) ----
typedef unsigned long long u64;
__device__ __forceinline__ void fma2(u64 &d, u64 a, u64 b) {
    asm("fma.rn.f32x2 %0, %1, %2, %3;" : "=l"(d) : "l"(a), "l"(b), "l"(d));
}
__device__ __forceinline__ u64 rep2(float x) {
    u64 r; unsigned int u = __float_as_uint(x);
    asm("mov.b64 %0, {%1,%1};" : "=l"(r) : "r"(u));
    return r;
}
__device__ __forceinline__ float lo2(u64 v) { return __uint_as_float((unsigned)v); }
__device__ __forceinline__ float hi2(u64 v) { return __uint_as_float((unsigned)(v >> 32)); }

// gated residual: sigmoid(x)*tanh(x) == (1-e^-x)/(1+e^-2x); clamp keeps it finite
__device__ __forceinline__ float gated(float p) {
    float pc = fminf(fmaxf(p, -20.f), 20.f);
    float u = __expf(-pc);
    return __fdividef(1.f - u, 1.f + u*u);
}

// ---------------- tiny precompute kernels ----------------
__global__ void k_SB(const float* __restrict__ a1, const float* __restrict__ a2,
                     const float* __restrict__ b1, const float* __restrict__ b2) {
    int idx = blockIdx.x*256 + threadIdx.x;
    if (idx >= NN2) return;
    int i = idx / NN, k = idx % NN;
    float s = 0.f, bm = 0.f;
#pragma unroll
    for (int m = 0; m < MM; m++) {
        s  += a1[i*MM+m] * a2[m*NN+k];
        bm += b1[i*MM+m] * b2[m*NN+k];
    }
    g_S[idx] = s; g_Bm[idx] = bm;
}

__global__ void k_Wp(const float* __restrict__ w1, const float* __restrict__ w2) {
    int idx = blockIdx.x*256 + threadIdx.x;
    if (idx >= NN*DD*DD) return;
    int n = idx / (DD*DD), r = idx % (DD*DD);
    float s = 0.f;
#pragma unroll
    for (int m = 0; m < MM; m++) s += w1[n*MM+m] * w2[m*DD*DD+r];
    g_W[idx] = s;
}

__global__ void k_gWT(const float* __restrict__ gcnW) {
    int idx = blockIdx.x*256 + threadIdx.x;
    if (idx >= 192*DD) return;
    int i  = idx & 3;
    int d  = (idx >> 2) & 63;
    int f4 = idx >> 8;
    g_gcnWT4[idx] = gcnW[d*192 + f4*4 + i];
}

// transpose X[b,d,n,t] -> Xp[bt][n][d]
__global__ void k_txp(const float* __restrict__ X) {
    int n = blockIdx.x, b = blockIdx.y;
    __shared__ float tile[DD][13];
    int tid = threadIdx.x;
#pragma unroll
    for (int i = 0; i < 3; i++) {
        int lin = tid + i*256;
        if (lin < DD*TT) {
            int d = lin / TT, t = lin % TT;
            tile[d][t] = X[(((size_t)b*DD+d)*NN+n)*TT + t];
        }
    }
    __syncthreads();
#pragma unroll
    for (int i = 0; i < 3; i++) {
        int lin = tid + i*256;
        if (lin < DD*TT) {
            int t = lin >> 6, d = lin & 63;
            g_Xp[(size_t)(b*TT+t)*ND + n*DD + d] = tile[d][t];
        }
    }
}

// ---------------- adjacency: A = relu(S * sin(te@adjW^T + adjB) + Bm) ----------------
// M flattened over (bt, n): 115200 rows = 900 tiles x 128, ZERO row waste.
// B (adjW) is shared across bt, so tiles may span bt boundaries freely.
// Mainloop identical to the validated R10 code.
__global__ void __launch_bounds__(128) k_adj(const float* __restrict__ te,
                                             const float* __restrict__ adjW,
                                             const float* __restrict__ adjB) {
    const int mtile = blockIdx.x % 900;
    const int ct    = blockIdx.x / 900;
    const int rowBase = mtile*128, colBase = ct*64;
    __shared__ __align__(16) float As_t[32][132];
    __shared__ __align__(16) float Bs[32][68];
    const int tid = threadIdx.x;
    const int tx = tid & 7;
    const int ty = tid >> 3;
    u64 acc[4][8] = {};

    // per-thread staging row (always valid)
    const int m  = rowBase + tid;
    const int sbt = m / NN, sn = m % NN;
    const int sb = sbt / TT, st = sbt % TT;
    const float* asrc = te + (((size_t)sb*NN + sn)*TT + st)*DD;

    for (int k0 = 0; k0 < DD; k0 += 32) {
        {
#pragma unroll
            for (int c = 0; c < 8; c++) {
                float4 v = *(const float4*)(asrc + k0 + 4*c);
                As_t[4*c+0][tid] = v.x; As_t[4*c+1][tid] = v.y;
                As_t[4*c+2][tid] = v.z; As_t[4*c+3][tid] = v.w;
            }
        }
#pragma unroll
        for (int i = 0; i < 4; i++) {
            int lin = tid + i*128;
            int col = lin >> 3, kc = lin & 7;
            int gcol = colBase + col;
            float4 v = (gcol < NN) ? *(const float4*)(adjW + gcol*DD + k0 + kc*4)
                                   : make_float4(0.f,0.f,0.f,0.f);
            Bs[kc*4+0][col] = v.x; Bs[kc*4+1][col] = v.y;
            Bs[kc*4+2][col] = v.z; Bs[kc*4+3][col] = v.w;
        }
        __syncthreads();
#pragma unroll 8
        for (int kk = 0; kk < 32; kk++) {
            ulonglong2 ap0 = *(const ulonglong2*)&As_t[kk][ty*8];
            ulonglong2 ap1 = *(const ulonglong2*)&As_t[kk][ty*8+4];
            float4 b0 = *(const float4*)&Bs[kk][tx*8];
            float4 b1 = *(const float4*)&Bs[kk][tx*8+4];
            u64 ap[4] = {ap0.x, ap0.y, ap1.x, ap1.y};
            u64 br[8] = {rep2(b0.x),rep2(b0.y),rep2(b0.z),rep2(b0.w),
                         rep2(b1.x),rep2(b1.y),rep2(b1.z),rep2(b1.w)};
#pragma unroll
            for (int i = 0; i < 4; i++)
#pragma unroll
                for (int j = 0; j < 8; j++)
                    fma2(acc[i][j], ap[i], br[j]);
        }
        __syncthreads();
    }

    // epilogue: sin / scale / relu (MUFU.SIN); rows always valid, cols masked
    const int c0 = colBase + tx*8;
#pragma unroll
    for (int i = 0; i < 4; i++) {
#pragma unroll
        for (int lane = 0; lane < 2; lane++) {
            int mr = rowBase + ty*8 + 2*i + lane;
            int rbt = mr / NN, rn = mr % NN;
            float* Aout = g_A + (size_t)rbt*NN2 + (size_t)rn*NN;
            const float* Sr  = g_S  + (size_t)rn*NN;
            const float* Bmr = g_Bm + (size_t)rn*NN;
#pragma unroll
            for (int j = 0; j < 8; j++) {
                int col = c0 + j;
                if (col >= NN) continue;
                float pre = lane ? hi2(acc[i][j]) : lo2(acc[i][j]);
                float v = __sinf(pre + adjB[col]);
                v = Sr[col]*v + Bmr[col];
                Aout[col] = v > 0.f ? v : 0.f;
            }
        }
    }
}

// ---------------- Tmp = A @ Hb  (per bt: [300,300]@[300,64]) ----------------
__global__ void __launch_bounds__(128) k_mm(int hop) {
    const int bt = blockIdx.y;
    const int rowBase = blockIdx.x*128;
    const float* Hb = (hop == 0) ? g_Xp : g_H1;
    const float* Abt = g_A + (size_t)bt*NN2;
    const float* Hbt = Hb + (size_t)bt*ND;
    __shared__ __align__(16) float As_t[32][132];
    __shared__ __align__(16) float Bs[32][68];
    const int tid = threadIdx.x;
    const int tx = tid & 7;
    const int ty = tid >> 3;
    u64 acc[4][8] = {};

    for (int k0 = 0; k0 < 320; k0 += 32) {
        {
            int row = rowBase + tid;
            const float* src = Abt + (size_t)row*NN + k0;
#pragma unroll
            for (int c = 0; c < 8; c++) {
                float4 v;
                if (row < NN && (k0 + 4*c + 3) < NN) v = *(const float4*)(src + 4*c);
                else v = make_float4(0.f,0.f,0.f,0.f);
                As_t[4*c+0][tid] = v.x; As_t[4*c+1][tid] = v.y;
                As_t[4*c+2][tid] = v.z; As_t[4*c+3][tid] = v.w;
            }
        }
#pragma unroll
        for (int i = 0; i < 4; i++) {
            int lin = tid + i*128;
            int kk = lin >> 4, d4 = lin & 15;
            int k = k0 + kk;
            float4 v = (k < NN) ? *(const float4*)(Hbt + (size_t)k*DD + d4*4)
                                : make_float4(0.f,0.f,0.f,0.f);
            *(float4*)&Bs[kk][d4*4] = v;
        }
        __syncthreads();
#pragma unroll 8
        for (int kk = 0; kk < 32; kk++) {
            ulonglong2 ap0 = *(const ulonglong2*)&As_t[kk][ty*8];
            ulonglong2 ap1 = *(const ulonglong2*)&As_t[kk][ty*8+4];
            float4 b0 = *(const float4*)&Bs[kk][tx*8];
            float4 b1 = *(const float4*)&Bs[kk][tx*8+4];
            u64 ap[4] = {ap0.x, ap0.y, ap1.x, ap1.y};
            u64 br[8] = {rep2(b0.x),rep2(b0.y),rep2(b0.z),rep2(b0.w),
                         rep2(b1.x),rep2(b1.y),rep2(b1.z),rep2(b1.w)};
#pragma unroll
            for (int i = 0; i < 4; i++)
#pragma unroll
                for (int j = 0; j < 8; j++)
                    fma2(acc[i][j], ap[i], br[j]);
        }
        __syncthreads();
    }

    float* Tbt = g_Tmp + (size_t)bt*ND;
    const int c0 = tx*8;
#pragma unroll
    for (int i = 0; i < 4; i++) {
        int r0 = rowBase + ty*8 + 2*i;
        if (r0 < NN) {
            *(float4*)&Tbt[(size_t)r0*DD + c0] =
                make_float4(lo2(acc[i][0]), lo2(acc[i][1]), lo2(acc[i][2]), lo2(acc[i][3]));
            *(float4*)&Tbt[(size_t)r0*DD + c0 + 4] =
                make_float4(lo2(acc[i][4]), lo2(acc[i][5]), lo2(acc[i][6]), lo2(acc[i][7]));
        }
        if (r0 + 1 < NN) {
            *(float4*)&Tbt[(size_t)(r0+1)*DD + c0] =
                make_float4(hi2(acc[i][0]), hi2(acc[i][1]), hi2(acc[i][2]), hi2(acc[i][3]));
            *(float4*)&Tbt[(size_t)(r0+1)*DD + c0 + 4] =
                make_float4(hi2(acc[i][4]), hi2(acc[i][5]), hi2(acc[i][6]), hi2(acc[i][7]));
        }
    }
}

// ---------------- per-node matmul + gated residual (FFMA2) ----------------
// H[bt,n,:] = gated(Xp[bt,n,:] + Tmp[bt,n,:] @ W[n])
// grid (3, N): rows = 128 bt (all valid, 384=3*128), cols = 64 d, K = 64
__global__ void __launch_bounds__(128) k_nodemm(int hop) {
    const int n = blockIdx.y;
    const int rowBase = blockIdx.x*128;          // bt tile base
    float* Hout = (hop == 0) ? g_H1 : g_H2;
    const float* Wn = g_W + (size_t)n*DD*DD;
    __shared__ __align__(16) float As_t[32][132];   // [kk][btRow]
    __shared__ __align__(16) float Bs[32][68];      // [kk][d]
    const int tid = threadIdx.x;
    const int tx = tid & 7;
    const int ty = tid >> 3;
    u64 acc[4][8] = {};

    for (int k0 = 0; k0 < DD; k0 += 32) {
        {
            const float* src = g_Tmp + (size_t)(rowBase + tid)*ND + n*DD + k0;
#pragma unroll
            for (int c = 0; c < 8; c++) {
                float4 v = *(const float4*)(src + 4*c);
                As_t[4*c+0][tid] = v.x; As_t[4*c+1][tid] = v.y;
                As_t[4*c+2][tid] = v.z; As_t[4*c+3][tid] = v.w;
            }
        }
#pragma unroll
        for (int i = 0; i < 4; i++) {
            int lin = tid + i*128;
            int kk = lin >> 4, d4 = lin & 15;
            *(float4*)&Bs[kk][d4*4] = *(const float4*)(Wn + (size_t)(k0+kk)*DD + d4*4);
        }
        __syncthreads();
#pragma unroll 8
        for (int kk = 0; kk < 32; kk++) {
            ulonglong2 ap0 = *(const ulonglong2*)&As_t[kk][ty*8];
            ulonglong2 ap1 = *(const ulonglong2*)&As_t[kk][ty*8+4];
            float4 b0 = *(const float4*)&Bs[kk][tx*8];
            float4 b1 = *(const float4*)&Bs[kk][tx*8+4];
            u64 ap[4] = {ap0.x, ap0.y, ap1.x, ap1.y};
            u64 br[8] = {rep2(b0.x),rep2(b0.y),rep2(b0.z),rep2(b0.w),
                         rep2(b1.x),rep2(b1.y),rep2(b1.z),rep2(b1.w)};
#pragma unroll
            for (int i = 0; i < 4; i++)
#pragma unroll
                for (int j = 0; j < 8; j++)
                    fma2(acc[i][j], ap[i], br[j]);
        }
        __syncthreads();
    }

    // epilogue: gated residual, vectorized per row
    const int c0 = tx*8;
#pragma unroll
    for (int i = 0; i < 4; i++) {
        int r0 = rowBase + ty*8 + 2*i;
#pragma unroll
        for (int lane = 0; lane < 2; lane++) {
            int bt = r0 + lane;
            size_t base = (size_t)bt*ND + n*DD + c0;
            float4 x0 = *(const float4*)(g_Xp + base);
            float4 x1 = *(const float4*)(g_Xp + base + 4);
            float v[8];
#pragma unroll
            for (int j = 0; j < 8; j++)
                v[j] = lane ? hi2(acc[i][j]) : lo2(acc[i][j]);
            float4 o0, o1;
            o0.x = gated(x0.x + v[0]); o0.y = gated(x0.y + v[1]);
            o0.z = gated(x0.z + v[2]); o0.w = gated(x0.w + v[3]);
            o1.x = gated(x1.x + v[4]); o1.y = gated(x1.y + v[5]);
            o1.z = gated(x1.z + v[6]); o1.w = gated(x1.w + v[7]);
            *(float4*)(Hout + base) = o0;
            *(float4*)(Hout + base + 4) = o1;
        }
    }
}

// ---------------- output: [Xp|H1|H2] @ gcnW^T + gcnB -> [B,D,N,T] ----------------
__global__ void __launch_bounds__(128) k_out(const float* __restrict__ gcnB,
                                             float* __restrict__ out) {
    const int b = blockIdx.y;
    const int nBase = blockIdx.x*4;
    __shared__ __align__(16) float Hc[4*12*192];
    const int tid = threadIdx.x;
    float4* Hc4 = (float4*)Hc;
#pragma unroll
    for (int i = 0; i < 18; i++) {
        int lin4 = tid + i*128;
        int nl = lin4 / 576;
        int rem = lin4 - nl*576;
        int t = rem / 48;
        int f4 = rem - t*48;
        int seg = f4 >> 4, fd4 = f4 & 15;
        const float* src = (seg == 0) ? g_Xp : ((seg == 1) ? g_H1 : g_H2);
        Hc4[lin4] = *(const float4*)(src + (size_t)(b*TT+t)*ND + (nBase+nl)*DD + fd4*4);
    }
    __syncthreads();
    const int d2 = tid & 31, nloc = tid >> 5;
    u64 acc[12][2] = {};
    const ulonglong2* WT = (const ulonglong2*)g_gcnWT4;
#pragma unroll 4
    for (int f4 = 0; f4 < 48; f4++) {
        ulonglong2 wA = WT[f4*64 + d2];
        ulonglong2 wB = WT[f4*64 + d2 + 32];
        const float* hb = &Hc[nloc*2304 + f4*4];
#pragma unroll
        for (int t = 0; t < 12; t++) {
            ulonglong2 hp = *(const ulonglong2*)&hb[t*192];
            fma2(acc[t][0], hp.x, wA.x);
            fma2(acc[t][0], hp.y, wA.y);
            fma2(acc[t][1], hp.x, wB.x);
            fma2(acc[t][1], hp.y, wB.y);
        }
    }
    const int n = nBase + nloc;
#pragma unroll
    for (int dsel = 0; dsel < 2; dsel++) {
        int d = d2 + dsel*32;
        float bias = gcnB[d];
        float* op = out + ((size_t)(b*DD+d)*NN + n)*TT;
        float v[12];
#pragma unroll
        for (int t = 0; t < 12; t++) v[t] = lo2(acc[t][dsel]) + hi2(acc[t][dsel]) + bias;
#pragma unroll
        for (int q = 0; q < 3; q++)
            *(float4*)&op[q*4] = make_float4(v[q*4], v[q*4+1], v[q*4+2], v[q*4+3]);
    }
}

// ---------------- launcher (k_adj stays in the ncu capture slot #4) --------
extern "C" void kernel_launch(void* const* d_in, const int* in_sizes, int n_in,
                              void* d_out, int out_size) {
    const float* X    = (const float*)d_in[0];
    const float* te   = (const float*)d_in[1];
    const float* adjW = (const float*)d_in[2];
    const float* adjB = (const float*)d_in[3];
    const float* tW1  = (const float*)d_in[4];
    const float* tW2  = (const float*)d_in[5];
    const float* a1   = (const float*)d_in[6];
    const float* a2   = (const float*)d_in[7];
    const float* b1   = (const float*)d_in[8];
    const float* b2   = (const float*)d_in[9];
    const float* gcnW = (const float*)d_in[10];
    const float* gcnB = (const float*)d_in[11];
    float* out = (float*)d_out;

    k_SB <<<(NN2 + 255)/256, 256>>>(a1, a2, b1, b2);          // 1
    k_txp<<<dim3(NN, BB), 256>>>(X);                          // 2
    k_Wp <<<(NN*DD*DD + 255)/256, 256>>>(tW1, tW2);           // 3
    k_adj<<<dim3(4500), 128>>>(te, adjW, adjB);               // 4  <- capture slot

    // hop 1
    k_mm    <<<dim3(3, BT), 128>>>(0);                        // 5
    k_nodemm<<<dim3(3, NN), 128>>>(0);                        // 6
    // hop 2
    k_mm    <<<dim3(3, BT), 128>>>(1);                        // 7
    k_nodemm<<<dim3(3, NN), 128>>>(1);                        // 8

    k_gWT<<<(192*DD + 255)/256, 256>>>(gcnW);                 // 9
    k_out<<<dim3(75, BB), 128>>>(gcnB, out);                  // 10
}

// round 14
// speedup vs baseline: 1.7885x; 1.1265x over previous
#include <cuda_runtime.h>
#include <math.h>

#define BB 32
#define NN 300
#define TT 12
#define DD 64
#define MM 16
#define BT (BB*TT)        // 384
#define ND (NN*DD)        // 19200
#define NN2 (NN*NN)       // 90000
#define MFLAT (BT*NN)     // 115200 = 900 * 128

// ---- scratch (device globals; no runtime allocation) ----
__device__ float g_S[NN2];             // alpha1@alpha2
__device__ float g_Bm[NN2];            // beta1@beta2
__device__ float g_W[NN*DD*DD];        // per-node weights [N,64,64]
__device__ float g_gcnWT4[192*DD];     // gcnW rearranged
__device__ float g_A[(size_t)BT*NN2];  // adjacency per (b,t)   ~138MB
__device__ float g_Xp[(size_t)BT*ND];  // X transposed [bt][n][d]
__device__ float g_H1[(size_t)BT*ND];
__device__ float g_H2[(size_t)BT*ND];
__device__ float g_Tmp[(size_t)BT*ND];

// ---- packed fp32x2 helpers (SASS FFMA2 path) ----
typedef unsigned long long u64;
__device__ __forceinline__ void fma2(u64 &d, u64 a, u64 b) {
    asm("fma.rn.f32x2 %0, %1, %2, %3;" : "=l"(d) : "l"(a), "l"(b), "l"(d));
}
__device__ __forceinline__ u64 rep2(float x) {
    u64 r; unsigned int u = __float_as_uint(x);
    asm("mov.b64 %0, {%1,%1};" : "=l"(r) : "r"(u));
    return r;
}
__device__ __forceinline__ float lo2(u64 v) { return __uint_as_float((unsigned)v); }
__device__ __forceinline__ float hi2(u64 v) { return __uint_as_float((unsigned)(v >> 32)); }

// gated residual: sigmoid(x)*tanh(x) == (1-e^-x)/(1+e^-2x); clamp keeps it finite
__device__ __forceinline__ float gated(float p) {
    float pc = fminf(fmaxf(p, -20.f), 20.f);
    float u = __expf(-pc);
    return __fdividef(1.f - u, 1.f + u*u);
}

// ---------------- tiny precompute kernels ----------------
__global__ void k_SB(const float* __restrict__ a1, const float* __restrict__ a2,
                     const float* __restrict__ b1, const float* __restrict__ b2) {
    int idx = blockIdx.x*256 + threadIdx.x;
    if (idx >= NN2) return;
    int i = idx / NN, k = idx % NN;
    float s = 0.f, bm = 0.f;
#pragma unroll
    for (int m = 0; m < MM; m++) {
        s  += a1[i*MM+m] * a2[m*NN+k];
        bm += b1[i*MM+m] * b2[m*NN+k];
    }
    g_S[idx] = s; g_Bm[idx] = bm;
}

__global__ void k_Wp(const float* __restrict__ w1, const float* __restrict__ w2) {
    int idx = blockIdx.x*256 + threadIdx.x;
    if (idx >= NN*DD*DD) return;
    int n = idx / (DD*DD), r = idx % (DD*DD);
    float s = 0.f;
#pragma unroll
    for (int m = 0; m < MM; m++) s += w1[n*MM+m] * w2[m*DD*DD+r];
    g_W[idx] = s;
}

__global__ void k_gWT(const float* __restrict__ gcnW) {
    int idx = blockIdx.x*256 + threadIdx.x;
    if (idx >= 192*DD) return;
    int i  = idx & 3;
    int d  = (idx >> 2) & 63;
    int f4 = idx >> 8;
    g_gcnWT4[idx] = gcnW[d*192 + f4*4 + i];
}

// transpose X[b,d,n,t] -> Xp[bt][n][d]
__global__ void k_txp(const float* __restrict__ X) {
    int n = blockIdx.x, b = blockIdx.y;
    __shared__ float tile[DD][13];
    int tid = threadIdx.x;
#pragma unroll
    for (int i = 0; i < 3; i++) {
        int lin = tid + i*256;
        if (lin < DD*TT) {
            int d = lin / TT, t = lin % TT;
            tile[d][t] = X[(((size_t)b*DD+d)*NN+n)*TT + t];
        }
    }
    __syncthreads();
#pragma unroll
    for (int i = 0; i < 3; i++) {
        int lin = tid + i*256;
        if (lin < DD*TT) {
            int t = lin >> 6, d = lin & 63;
            g_Xp[(size_t)(b*TT+t)*ND + n*DD + d] = tile[d][t];
        }
    }
}

// ---------------- adjacency: A = relu(S * sin(te@adjW^T + adjB) + Bm) ----------------
// M flattened over (bt, n): 115200 rows = 900 tiles x 128, zero row waste.
// Mainloop identical to R12; epilogue vectorized (LDG.128/STG.128).
__global__ void __launch_bounds__(128) k_adj(const float* __restrict__ te,
                                             const float* __restrict__ adjW,
                                             const float* __restrict__ adjB) {
    const int mtile = blockIdx.x % 900;
    const int ct    = blockIdx.x / 900;
    const int rowBase = mtile*128, colBase = ct*64;
    __shared__ __align__(16) float As_t[32][132];
    __shared__ __align__(16) float Bs[32][68];
    const int tid = threadIdx.x;
    const int tx = tid & 7;
    const int ty = tid >> 3;
    u64 acc[4][8] = {};

    // per-thread staging row (always valid)
    const int m  = rowBase + tid;
    const int sbt = m / NN, sn = m % NN;
    const int sb = sbt / TT, st = sbt % TT;
    const float* asrc = te + (((size_t)sb*NN + sn)*TT + st)*DD;

    for (int k0 = 0; k0 < DD; k0 += 32) {
        {
#pragma unroll
            for (int c = 0; c < 8; c++) {
                float4 v = *(const float4*)(asrc + k0 + 4*c);
                As_t[4*c+0][tid] = v.x; As_t[4*c+1][tid] = v.y;
                As_t[4*c+2][tid] = v.z; As_t[4*c+3][tid] = v.w;
            }
        }
#pragma unroll
        for (int i = 0; i < 4; i++) {
            int lin = tid + i*128;
            int col = lin >> 3, kc = lin & 7;
            int gcol = colBase + col;
            float4 v = (gcol < NN) ? *(const float4*)(adjW + gcol*DD + k0 + kc*4)
                                   : make_float4(0.f,0.f,0.f,0.f);
            Bs[kc*4+0][col] = v.x; Bs[kc*4+1][col] = v.y;
            Bs[kc*4+2][col] = v.z; Bs[kc*4+3][col] = v.w;
        }
        __syncthreads();
#pragma unroll 8
        for (int kk = 0; kk < 32; kk++) {
            ulonglong2 ap0 = *(const ulonglong2*)&As_t[kk][ty*8];
            ulonglong2 ap1 = *(const ulonglong2*)&As_t[kk][ty*8+4];
            float4 b0 = *(const float4*)&Bs[kk][tx*8];
            float4 b1 = *(const float4*)&Bs[kk][tx*8+4];
            u64 ap[4] = {ap0.x, ap0.y, ap1.x, ap1.y};
            u64 br[8] = {rep2(b0.x),rep2(b0.y),rep2(b0.z),rep2(b0.w),
                         rep2(b1.x),rep2(b1.y),rep2(b1.z),rep2(b1.w)};
#pragma unroll
            for (int i = 0; i < 4; i++)
#pragma unroll
                for (int j = 0; j < 8; j++)
                    fma2(acc[i][j], ap[i], br[j]);
        }
        __syncthreads();
    }

    // epilogue: sin / scale / relu. Rows always valid. Vector path when the
    // thread's 8 consecutive cols are all < NN; scalar masked path otherwise.
    const int c0 = colBase + tx*8;
    if (c0 + 7 < NN) {
        float4 ab0 = *(const float4*)(adjB + c0);
        float4 ab1 = *(const float4*)(adjB + c0 + 4);
        const float bias[8] = {ab0.x,ab0.y,ab0.z,ab0.w,ab1.x,ab1.y,ab1.z,ab1.w};
#pragma unroll
        for (int i = 0; i < 4; i++) {
#pragma unroll
            for (int lane = 0; lane < 2; lane++) {
                int mr = rowBase + ty*8 + 2*i + lane;
                int rbt = mr / NN, rn = mr - rbt*NN;
                const float* Sr  = g_S  + (size_t)rn*NN + c0;
                const float* Bmr = g_Bm + (size_t)rn*NN + c0;
                float4 s0 = *(const float4*)Sr,  s1 = *(const float4*)(Sr+4);
                float4 m0 = *(const float4*)Bmr, m1 = *(const float4*)(Bmr+4);
                const float sv[8] = {s0.x,s0.y,s0.z,s0.w,s1.x,s1.y,s1.z,s1.w};
                const float mv[8] = {m0.x,m0.y,m0.z,m0.w,m1.x,m1.y,m1.z,m1.w};
                float o[8];
#pragma unroll
                for (int j = 0; j < 8; j++) {
                    float pre = lane ? hi2(acc[i][j]) : lo2(acc[i][j]);
                    float v = __sinf(pre + bias[j]);
                    v = sv[j]*v + mv[j];
                    o[j] = v > 0.f ? v : 0.f;
                }
                float* Aout = g_A + (size_t)rbt*NN2 + (size_t)rn*NN + c0;
                *(float4*)Aout     = make_float4(o[0],o[1],o[2],o[3]);
                *(float4*)(Aout+4) = make_float4(o[4],o[5],o[6],o[7]);
            }
        }
    } else {
#pragma unroll
        for (int i = 0; i < 4; i++) {
#pragma unroll
            for (int lane = 0; lane < 2; lane++) {
                int mr = rowBase + ty*8 + 2*i + lane;
                int rbt = mr / NN, rn = mr - rbt*NN;
                float* Aout = g_A + (size_t)rbt*NN2 + (size_t)rn*NN;
                const float* Sr  = g_S  + (size_t)rn*NN;
                const float* Bmr = g_Bm + (size_t)rn*NN;
#pragma unroll
                for (int j = 0; j < 8; j++) {
                    int col = c0 + j;
                    if (col >= NN) continue;
                    float pre = lane ? hi2(acc[i][j]) : lo2(acc[i][j]);
                    float v = __sinf(pre + adjB[col]);
                    v = Sr[col]*v + Bmr[col];
                    Aout[col] = v > 0.f ? v : 0.f;
                }
            }
        }
    }
}

// ---------------- Tmp = A @ Hb  (per bt: [300,300]@[300,64]) ----------------
__global__ void __launch_bounds__(128) k_mm(int hop) {
    const int bt = blockIdx.y;
    const int rowBase = blockIdx.x*128;
    const float* Hb = (hop == 0) ? g_Xp : g_H1;
    const float* Abt = g_A + (size_t)bt*NN2;
    const float* Hbt = Hb + (size_t)bt*ND;
    __shared__ __align__(16) float As_t[32][132];
    __shared__ __align__(16) float Bs[32][68];
    const int tid = threadIdx.x;
    const int tx = tid & 7;
    const int ty = tid >> 3;
    u64 acc[4][8] = {};

    for (int k0 = 0; k0 < 320; k0 += 32) {
        {
            int row = rowBase + tid;
            const float* src = Abt + (size_t)row*NN + k0;
#pragma unroll
            for (int c = 0; c < 8; c++) {
                float4 v;
                if (row < NN && (k0 + 4*c + 3) < NN) v = *(const float4*)(src + 4*c);
                else v = make_float4(0.f,0.f,0.f,0.f);
                As_t[4*c+0][tid] = v.x; As_t[4*c+1][tid] = v.y;
                As_t[4*c+2][tid] = v.z; As_t[4*c+3][tid] = v.w;
            }
        }
#pragma unroll
        for (int i = 0; i < 4; i++) {
            int lin = tid + i*128;
            int kk = lin >> 4, d4 = lin & 15;
            int k = k0 + kk;
            float4 v = (k < NN) ? *(const float4*)(Hbt + (size_t)k*DD + d4*4)
                                : make_float4(0.f,0.f,0.f,0.f);
            *(float4*)&Bs[kk][d4*4] = v;
        }
        __syncthreads();
#pragma unroll 8
        for (int kk = 0; kk < 32; kk++) {
            ulonglong2 ap0 = *(const ulonglong2*)&As_t[kk][ty*8];
            ulonglong2 ap1 = *(const ulonglong2*)&As_t[kk][ty*8+4];
            float4 b0 = *(const float4*)&Bs[kk][tx*8];
            float4 b1 = *(const float4*)&Bs[kk][tx*8+4];
            u64 ap[4] = {ap0.x, ap0.y, ap1.x, ap1.y};
            u64 br[8] = {rep2(b0.x),rep2(b0.y),rep2(b0.z),rep2(b0.w),
                         rep2(b1.x),rep2(b1.y),rep2(b1.z),rep2(b1.w)};
#pragma unroll
            for (int i = 0; i < 4; i++)
#pragma unroll
                for (int j = 0; j < 8; j++)
                    fma2(acc[i][j], ap[i], br[j]);
        }
        __syncthreads();
    }

    float* Tbt = g_Tmp + (size_t)bt*ND;
    const int c0 = tx*8;
#pragma unroll
    for (int i = 0; i < 4; i++) {
        int r0 = rowBase + ty*8 + 2*i;
        if (r0 < NN) {
            *(float4*)&Tbt[(size_t)r0*DD + c0] =
                make_float4(lo2(acc[i][0]), lo2(acc[i][1]), lo2(acc[i][2]), lo2(acc[i][3]));
            *(float4*)&Tbt[(size_t)r0*DD + c0 + 4] =
                make_float4(lo2(acc[i][4]), lo2(acc[i][5]), lo2(acc[i][6]), lo2(acc[i][7]));
        }
        if (r0 + 1 < NN) {
            *(float4*)&Tbt[(size_t)(r0+1)*DD + c0] =
                make_float4(hi2(acc[i][0]), hi2(acc[i][1]), hi2(acc[i][2]), hi2(acc[i][3]));
            *(float4*)&Tbt[(size_t)(r0+1)*DD + c0 + 4] =
                make_float4(hi2(acc[i][4]), hi2(acc[i][5]), hi2(acc[i][6]), hi2(acc[i][7]));
        }
    }
}

// ---------------- per-node matmul + gated residual (FFMA2) ----------------
__global__ void __launch_bounds__(128) k_nodemm(int hop) {
    const int n = blockIdx.y;
    const int rowBase = blockIdx.x*128;
    float* Hout = (hop == 0) ? g_H1 : g_H2;
    const float* Wn = g_W + (size_t)n*DD*DD;
    __shared__ __align__(16) float As_t[32][132];
    __shared__ __align__(16) float Bs[32][68];
    const int tid = threadIdx.x;
    const int tx = tid & 7;
    const int ty = tid >> 3;
    u64 acc[4][8] = {};

    for (int k0 = 0; k0 < DD; k0 += 32) {
        {
            const float* src = g_Tmp + (size_t)(rowBase + tid)*ND + n*DD + k0;
#pragma unroll
            for (int c = 0; c < 8; c++) {
                float4 v = *(const float4*)(src + 4*c);
                As_t[4*c+0][tid] = v.x; As_t[4*c+1][tid] = v.y;
                As_t[4*c+2][tid] = v.z; As_t[4*c+3][tid] = v.w;
            }
        }
#pragma unroll
        for (int i = 0; i < 4; i++) {
            int lin = tid + i*128;
            int kk = lin >> 4, d4 = lin & 15;
            *(float4*)&Bs[kk][d4*4] = *(const float4*)(Wn + (size_t)(k0+kk)*DD + d4*4);
        }
        __syncthreads();
#pragma unroll 8
        for (int kk = 0; kk < 32; kk++) {
            ulonglong2 ap0 = *(const ulonglong2*)&As_t[kk][ty*8];
            ulonglong2 ap1 = *(const ulonglong2*)&As_t[kk][ty*8+4];
            float4 b0 = *(const float4*)&Bs[kk][tx*8];
            float4 b1 = *(const float4*)&Bs[kk][tx*8+4];
            u64 ap[4] = {ap0.x, ap0.y, ap1.x, ap1.y};
            u64 br[8] = {rep2(b0.x),rep2(b0.y),rep2(b0.z),rep2(b0.w),
                         rep2(b1.x),rep2(b1.y),rep2(b1.z),rep2(b1.w)};
#pragma unroll
            for (int i = 0; i < 4; i++)
#pragma unroll
                for (int j = 0; j < 8; j++)
                    fma2(acc[i][j], ap[i], br[j]);
        }
        __syncthreads();
    }

    const int c0 = tx*8;
#pragma unroll
    for (int i = 0; i < 4; i++) {
        int r0 = rowBase + ty*8 + 2*i;
#pragma unroll
        for (int lane = 0; lane < 2; lane++) {
            int bt = r0 + lane;
            size_t base = (size_t)bt*ND + n*DD + c0;
            float4 x0 = *(const float4*)(g_Xp + base);
            float4 x1 = *(const float4*)(g_Xp + base + 4);
            float v[8];
#pragma unroll
            for (int j = 0; j < 8; j++)
                v[j] = lane ? hi2(acc[i][j]) : lo2(acc[i][j]);
            float4 o0, o1;
            o0.x = gated(x0.x + v[0]); o0.y = gated(x0.y + v[1]);
            o0.z = gated(x0.z + v[2]); o0.w = gated(x0.w + v[3]);
            o1.x = gated(x1.x + v[4]); o1.y = gated(x1.y + v[5]);
            o1.z = gated(x1.z + v[6]); o1.w = gated(x1.w + v[7]);
            *(float4*)(Hout + base) = o0;
            *(float4*)(Hout + base + 4) = o1;
        }
    }
}

// ---------------- output: [Xp|H1|H2] @ gcnW^T + gcnB -> [B,D,N,T] ----------------
__global__ void __launch_bounds__(128) k_out(const float* __restrict__ gcnB,
                                             float* __restrict__ out) {
    const int b = blockIdx.y;
    const int nBase = blockIdx.x*4;
    __shared__ __align__(16) float Hc[4*12*192];
    const int tid = threadIdx.x;
    float4* Hc4 = (float4*)Hc;
#pragma unroll
    for (int i = 0; i < 18; i++) {
        int lin4 = tid + i*128;
        int nl = lin4 / 576;
        int rem = lin4 - nl*576;
        int t = rem / 48;
        int f4 = rem - t*48;
        int seg = f4 >> 4, fd4 = f4 & 15;
        const float* src = (seg == 0) ? g_Xp : ((seg == 1) ? g_H1 : g_H2);
        Hc4[lin4] = *(const float4*)(src + (size_t)(b*TT+t)*ND + (nBase+nl)*DD + fd4*4);
    }
    __syncthreads();
    const int d2 = tid & 31, nloc = tid >> 5;
    u64 acc[12][2] = {};
    const ulonglong2* WT = (const ulonglong2*)g_gcnWT4;
#pragma unroll 4
    for (int f4 = 0; f4 < 48; f4++) {
        ulonglong2 wA = WT[f4*64 + d2];
        ulonglong2 wB = WT[f4*64 + d2 + 32];
        const float* hb = &Hc[nloc*2304 + f4*4];
#pragma unroll
        for (int t = 0; t < 12; t++) {
            ulonglong2 hp = *(const ulonglong2*)&hb[t*192];
            fma2(acc[t][0], hp.x, wA.x);
            fma2(acc[t][0], hp.y, wA.y);
            fma2(acc[t][1], hp.x, wB.x);
            fma2(acc[t][1], hp.y, wB.y);
        }
    }
    const int n = nBase + nloc;
#pragma unroll
    for (int dsel = 0; dsel < 2; dsel++) {
        int d = d2 + dsel*32;
        float bias = gcnB[d];
        float* op = out + ((size_t)(b*DD+d)*NN + n)*TT;
        float v[12];
#pragma unroll
        for (int t = 0; t < 12; t++) v[t] = lo2(acc[t][dsel]) + hi2(acc[t][dsel]) + bias;
#pragma unroll
        for (int q = 0; q < 3; q++)
            *(float4*)&op[q*4] = make_float4(v[q*4], v[q*4+1], v[q*4+2], v[q*4+3]);
    }
}

// ---------------- launcher (k_adj stays in the ncu capture slot #4) --------
extern "C" void kernel_launch(void* const* d_in, const int* in_sizes, int n_in,
                              void* d_out, int out_size) {
    const float* X    = (const float*)d_in[0];
    const float* te   = (const float*)d_in[1];
    const float* adjW = (const float*)d_in[2];
    const float* adjB = (const float*)d_in[3];
    const float* tW1  = (const float*)d_in[4];
    const float* tW2  = (const float*)d_in[5];
    const float* a1   = (const float*)d_in[6];
    const float* a2   = (const float*)d_in[7];
    const float* b1   = (const float*)d_in[8];
    const float* b2   = (const float*)d_in[9];
    const float* gcnW = (const float*)d_in[10];
    const float* gcnB = (const float*)d_in[11];
    float* out = (float*)d_out;

    k_SB <<<(NN2 + 255)/256, 256>>>(a1, a2, b1, b2);          // 1
    k_txp<<<dim3(NN, BB), 256>>>(X);                          // 2
    k_Wp <<<(NN*DD*DD + 255)/256, 256>>>(tW1, tW2);           // 3
    k_adj<<<dim3(4500), 128>>>(te, adjW, adjB);               // 4  <- capture slot

    // hop 1
    k_mm    <<<dim3(3, BT), 128>>>(0);                        // 5
    k_nodemm<<<dim3(3, NN), 128>>>(0);                        // 6
    // hop 2
    k_mm    <<<dim3(3, BT), 128>>>(1);                        // 7
    k_nodemm<<<dim3(3, NN), 128>>>(1);                        // 8

    k_gWT<<<(192*DD + 255)/256, 256>>>(gcnW);                 // 9
    k_out<<<dim3(75, BB), 128>>>(gcnB, out);                  // 10
}

// round 15
// speedup vs baseline: 2.1566x; 1.2058x over previous
#include <cuda_runtime.h>
#include <math.h>

#define BB 32
#define NN 300
#define TT 12
#define DD 64
#define MM 16
#define BT (BB*TT)        // 384
#define ND (NN*DD)        // 19200
#define NN2 (NN*NN)       // 90000
#define MFLAT (BT*NN)     // 115200 = 900 * 128

// ---- scratch (device globals; no runtime allocation) ----
__device__ float g_S[NN2];             // alpha1@alpha2
__device__ float g_Bm[NN2];            // beta1@beta2
__device__ float g_W[NN*DD*DD];        // per-node weights [N,64,64]
__device__ float g_gcnWT4[192*DD];     // gcnW rearranged
__device__ float g_A[(size_t)BT*NN2];  // adjacency per (b,t)   ~138MB
__device__ float g_Xp[(size_t)BT*ND];  // X transposed [bt][n][d]
__device__ float g_H1[(size_t)BT*ND];
__device__ float g_H2[(size_t)BT*ND];
__device__ float g_Tmp[(size_t)BT*ND];

// ---- packed fp32x2 helpers (SASS FFMA2 path) ----
typedef unsigned long long u64;
__device__ __forceinline__ void fma2(u64 &d, u64 a, u64 b) {
    asm("fma.rn.f32x2 %0, %1, %2, %3;" : "=l"(d) : "l"(a), "l"(b), "l"(d));
}
__device__ __forceinline__ u64 rep2(float x) {
    u64 r; unsigned int u = __float_as_uint(x);
    asm("mov.b64 %0, {%1,%1};" : "=l"(r) : "r"(u));
    return r;
}
__device__ __forceinline__ float lo2(u64 v) { return __uint_as_float((unsigned)v); }
__device__ __forceinline__ float hi2(u64 v) { return __uint_as_float((unsigned)(v >> 32)); }

// gated residual: sigmoid(x)*tanh(x) == (1-e^-x)/(1+e^-2x); clamp keeps it finite
__device__ __forceinline__ float gated(float p) {
    float pc = fminf(fmaxf(p, -20.f), 20.f);
    float u = __expf(-pc);
    return __fdividef(1.f - u, 1.f + u*u);
}

// ---------------- tiny precompute kernels ----------------
__global__ void k_SB(const float* __restrict__ a1, const float* __restrict__ a2,
                     const float* __restrict__ b1, const float* __restrict__ b2) {
    int idx = blockIdx.x*256 + threadIdx.x;
    if (idx >= NN2) return;
    int i = idx / NN, k = idx % NN;
    float s = 0.f, bm = 0.f;
#pragma unroll
    for (int m = 0; m < MM; m++) {
        s  += a1[i*MM+m] * a2[m*NN+k];
        bm += b1[i*MM+m] * b2[m*NN+k];
    }
    g_S[idx] = s; g_Bm[idx] = bm;
}

__global__ void k_Wp(const float* __restrict__ w1, const float* __restrict__ w2) {
    int idx = blockIdx.x*256 + threadIdx.x;
    if (idx >= NN*DD*DD) return;
    int n = idx / (DD*DD), r = idx % (DD*DD);
    float s = 0.f;
#pragma unroll
    for (int m = 0; m < MM; m++) s += w1[n*MM+m] * w2[m*DD*DD+r];
    g_W[idx] = s;
}

__global__ void k_gWT(const float* __restrict__ gcnW) {
    int idx = blockIdx.x*256 + threadIdx.x;
    if (idx >= 192*DD) return;
    int i  = idx & 3;
    int d  = (idx >> 2) & 63;
    int f4 = idx >> 8;
    g_gcnWT4[idx] = gcnW[d*192 + f4*4 + i];
}

// transpose X[b,d,n,t] -> Xp[bt][n][d]
__global__ void k_txp(const float* __restrict__ X) {
    int n = blockIdx.x, b = blockIdx.y;
    __shared__ float tile[DD][13];
    int tid = threadIdx.x;
#pragma unroll
    for (int i = 0; i < 3; i++) {
        int lin = tid + i*256;
        if (lin < DD*TT) {
            int d = lin / TT, t = lin % TT;
            tile[d][t] = X[(((size_t)b*DD+d)*NN+n)*TT + t];
        }
    }
    __syncthreads();
#pragma unroll
    for (int i = 0; i < 3; i++) {
        int lin = tid + i*256;
        if (lin < DD*TT) {
            int t = lin >> 6, d = lin & 63;
            g_Xp[(size_t)(b*TT+t)*ND + n*DD + d] = tile[d][t];
        }
    }
}

// ---------------- adjacency: A = relu(S * sin(te@adjW^T + adjB) + Bm) ----------------
// M flattened over (bt, n): 115200 rows = 900 tiles x 128, zero row waste.
// B columns split-mapped: thread covers cols {tx*4..+3, 32+tx*4..+3} so both
// B LDS.128 reads are contiguous 128B across the warp (conflict-free).
__global__ void __launch_bounds__(128) k_adj(const float* __restrict__ te,
                                             const float* __restrict__ adjW,
                                             const float* __restrict__ adjB) {
    const int mtile = blockIdx.x % 900;
    const int ct    = blockIdx.x / 900;
    const int rowBase = mtile*128, colBase = ct*64;
    __shared__ __align__(16) float As_t[32][132];
    __shared__ __align__(16) float Bs[32][68];
    const int tid = threadIdx.x;
    const int tx = tid & 7;
    const int ty = tid >> 3;
    u64 acc[4][8] = {};

    // per-thread staging row (always valid)
    const int m  = rowBase + tid;
    const int sbt = m / NN, sn = m % NN;
    const int sb = sbt / TT, st = sbt % TT;
    const float* asrc = te + (((size_t)sb*NN + sn)*TT + st)*DD;

    for (int k0 = 0; k0 < DD; k0 += 32) {
        {
#pragma unroll
            for (int c = 0; c < 8; c++) {
                float4 v = *(const float4*)(asrc + k0 + 4*c);
                As_t[4*c+0][tid] = v.x; As_t[4*c+1][tid] = v.y;
                As_t[4*c+2][tid] = v.z; As_t[4*c+3][tid] = v.w;
            }
        }
#pragma unroll
        for (int i = 0; i < 4; i++) {
            int lin = tid + i*128;
            int col = lin >> 3, kc = lin & 7;
            int gcol = colBase + col;
            float4 v = (gcol < NN) ? *(const float4*)(adjW + gcol*DD + k0 + kc*4)
                                   : make_float4(0.f,0.f,0.f,0.f);
            Bs[kc*4+0][col] = v.x; Bs[kc*4+1][col] = v.y;
            Bs[kc*4+2][col] = v.z; Bs[kc*4+3][col] = v.w;
        }
        __syncthreads();
#pragma unroll 8
        for (int kk = 0; kk < 32; kk++) {
            ulonglong2 ap0 = *(const ulonglong2*)&As_t[kk][ty*8];
            ulonglong2 ap1 = *(const ulonglong2*)&As_t[kk][ty*8+4];
            float4 b0 = *(const float4*)&Bs[kk][tx*4];        // contiguous 128B
            float4 b1 = *(const float4*)&Bs[kk][32 + tx*4];   // contiguous 128B
            u64 ap[4] = {ap0.x, ap0.y, ap1.x, ap1.y};
            u64 br[8] = {rep2(b0.x),rep2(b0.y),rep2(b0.z),rep2(b0.w),
                         rep2(b1.x),rep2(b1.y),rep2(b1.z),rep2(b1.w)};
#pragma unroll
            for (int i = 0; i < 4; i++)
#pragma unroll
                for (int j = 0; j < 8; j++)
                    fma2(acc[i][j], ap[i], br[j]);
        }
        __syncthreads();
    }

    // epilogue: sin / scale / relu. Column groups are 4-aligned and NN%4==0,
    // so each group is either fully valid or fully out of range.
    const int cA = colBase + tx*4;        // always < 288 <= NN-4+1 -> valid
    const int cB = cA + 32;               // may exceed NN
    const bool bvB = (cB + 3) < NN;
    float4 abA = *(const float4*)(adjB + cA);
    float4 abB = bvB ? *(const float4*)(adjB + cB) : make_float4(0,0,0,0);
    const float biasA[4] = {abA.x,abA.y,abA.z,abA.w};
    const float biasB[4] = {abB.x,abB.y,abB.z,abB.w};
#pragma unroll
    for (int i = 0; i < 4; i++) {
#pragma unroll
        for (int lane = 0; lane < 2; lane++) {
            int mr = rowBase + ty*8 + 2*i + lane;
            int rbt = mr / NN, rn = mr - rbt*NN;
            float* Aout = g_A + (size_t)rbt*NN2 + (size_t)rn*NN;
            const float* Sr  = g_S  + (size_t)rn*NN;
            const float* Bmr = g_Bm + (size_t)rn*NN;
            {
                float4 s = *(const float4*)(Sr + cA);
                float4 bm = *(const float4*)(Bmr + cA);
                const float sv[4] = {s.x,s.y,s.z,s.w};
                const float mv[4] = {bm.x,bm.y,bm.z,bm.w};
                float o[4];
#pragma unroll
                for (int j = 0; j < 4; j++) {
                    float pre = lane ? hi2(acc[i][j]) : lo2(acc[i][j]);
                    float v = __sinf(pre + biasA[j]);
                    v = sv[j]*v + mv[j];
                    o[j] = v > 0.f ? v : 0.f;
                }
                *(float4*)(Aout + cA) = make_float4(o[0],o[1],o[2],o[3]);
            }
            if (bvB) {
                float4 s = *(const float4*)(Sr + cB);
                float4 bm = *(const float4*)(Bmr + cB);
                const float sv[4] = {s.x,s.y,s.z,s.w};
                const float mv[4] = {bm.x,bm.y,bm.z,bm.w};
                float o[4];
#pragma unroll
                for (int j = 0; j < 4; j++) {
                    float pre = lane ? hi2(acc[i][j+4]) : lo2(acc[i][j+4]);
                    float v = __sinf(pre + biasB[j]);
                    v = sv[j]*v + mv[j];
                    o[j] = v > 0.f ? v : 0.f;
                }
                *(float4*)(Aout + cB) = make_float4(o[0],o[1],o[2],o[3]);
            }
        }
    }
}

// ---------------- Tmp = A @ Hb  (per bt: [300,300]@[300,64]) ----------------
__global__ void __launch_bounds__(128) k_mm(int hop) {
    const int bt = blockIdx.y;
    const int rowBase = blockIdx.x*128;
    const float* Hb = (hop == 0) ? g_Xp : g_H1;
    const float* Abt = g_A + (size_t)bt*NN2;
    const float* Hbt = Hb + (size_t)bt*ND;
    __shared__ __align__(16) float As_t[32][132];
    __shared__ __align__(16) float Bs[32][68];
    const int tid = threadIdx.x;
    const int tx = tid & 7;
    const int ty = tid >> 3;
    u64 acc[4][8] = {};

    for (int k0 = 0; k0 < 320; k0 += 32) {
        {
            int row = rowBase + tid;
            const float* src = Abt + (size_t)row*NN + k0;
#pragma unroll
            for (int c = 0; c < 8; c++) {
                float4 v;
                if (row < NN && (k0 + 4*c + 3) < NN) v = *(const float4*)(src + 4*c);
                else v = make_float4(0.f,0.f,0.f,0.f);
                As_t[4*c+0][tid] = v.x; As_t[4*c+1][tid] = v.y;
                As_t[4*c+2][tid] = v.z; As_t[4*c+3][tid] = v.w;
            }
        }
#pragma unroll
        for (int i = 0; i < 4; i++) {
            int lin = tid + i*128;
            int kk = lin >> 4, d4 = lin & 15;
            int k = k0 + kk;
            float4 v = (k < NN) ? *(const float4*)(Hbt + (size_t)k*DD + d4*4)
                                : make_float4(0.f,0.f,0.f,0.f);
            *(float4*)&Bs[kk][d4*4] = v;
        }
        __syncthreads();
#pragma unroll 8
        for (int kk = 0; kk < 32; kk++) {
            ulonglong2 ap0 = *(const ulonglong2*)&As_t[kk][ty*8];
            ulonglong2 ap1 = *(const ulonglong2*)&As_t[kk][ty*8+4];
            float4 b0 = *(const float4*)&Bs[kk][tx*4];
            float4 b1 = *(const float4*)&Bs[kk][32 + tx*4];
            u64 ap[4] = {ap0.x, ap0.y, ap1.x, ap1.y};
            u64 br[8] = {rep2(b0.x),rep2(b0.y),rep2(b0.z),rep2(b0.w),
                         rep2(b1.x),rep2(b1.y),rep2(b1.z),rep2(b1.w)};
#pragma unroll
            for (int i = 0; i < 4; i++)
#pragma unroll
                for (int j = 0; j < 8; j++)
                    fma2(acc[i][j], ap[i], br[j]);
        }
        __syncthreads();
    }

    float* Tbt = g_Tmp + (size_t)bt*ND;
    const int cA = tx*4, cB = cA + 32;
#pragma unroll
    for (int i = 0; i < 4; i++) {
        int r0 = rowBase + ty*8 + 2*i;
        if (r0 < NN) {
            *(float4*)&Tbt[(size_t)r0*DD + cA] =
                make_float4(lo2(acc[i][0]), lo2(acc[i][1]), lo2(acc[i][2]), lo2(acc[i][3]));
            *(float4*)&Tbt[(size_t)r0*DD + cB] =
                make_float4(lo2(acc[i][4]), lo2(acc[i][5]), lo2(acc[i][6]), lo2(acc[i][7]));
        }
        if (r0 + 1 < NN) {
            *(float4*)&Tbt[(size_t)(r0+1)*DD + cA] =
                make_float4(hi2(acc[i][0]), hi2(acc[i][1]), hi2(acc[i][2]), hi2(acc[i][3]));
            *(float4*)&Tbt[(size_t)(r0+1)*DD + cB] =
                make_float4(hi2(acc[i][4]), hi2(acc[i][5]), hi2(acc[i][6]), hi2(acc[i][7]));
        }
    }
}

// ---------------- per-node matmul + gated residual (FFMA2) ----------------
__global__ void __launch_bounds__(128) k_nodemm(int hop) {
    const int n = blockIdx.y;
    const int rowBase = blockIdx.x*128;
    float* Hout = (hop == 0) ? g_H1 : g_H2;
    const float* Wn = g_W + (size_t)n*DD*DD;
    __shared__ __align__(16) float As_t[32][132];
    __shared__ __align__(16) float Bs[32][68];
    const int tid = threadIdx.x;
    const int tx = tid & 7;
    const int ty = tid >> 3;
    u64 acc[4][8] = {};

    for (int k0 = 0; k0 < DD; k0 += 32) {
        {
            const float* src = g_Tmp + (size_t)(rowBase + tid)*ND + n*DD + k0;
#pragma unroll
            for (int c = 0; c < 8; c++) {
                float4 v = *(const float4*)(src + 4*c);
                As_t[4*c+0][tid] = v.x; As_t[4*c+1][tid] = v.y;
                As_t[4*c+2][tid] = v.z; As_t[4*c+3][tid] = v.w;
            }
        }
#pragma unroll
        for (int i = 0; i < 4; i++) {
            int lin = tid + i*128;
            int kk = lin >> 4, d4 = lin & 15;
            *(float4*)&Bs[kk][d4*4] = *(const float4*)(Wn + (size_t)(k0+kk)*DD + d4*4);
        }
        __syncthreads();
#pragma unroll 8
        for (int kk = 0; kk < 32; kk++) {
            ulonglong2 ap0 = *(const ulonglong2*)&As_t[kk][ty*8];
            ulonglong2 ap1 = *(const ulonglong2*)&As_t[kk][ty*8+4];
            float4 b0 = *(const float4*)&Bs[kk][tx*4];
            float4 b1 = *(const float4*)&Bs[kk][32 + tx*4];
            u64 ap[4] = {ap0.x, ap0.y, ap1.x, ap1.y};
            u64 br[8] = {rep2(b0.x),rep2(b0.y),rep2(b0.z),rep2(b0.w),
                         rep2(b1.x),rep2(b1.y),rep2(b1.z),rep2(b1.w)};
#pragma unroll
            for (int i = 0; i < 4; i++)
#pragma unroll
                for (int j = 0; j < 8; j++)
                    fma2(acc[i][j], ap[i], br[j]);
        }
        __syncthreads();
    }

    const int cA = tx*4, cB = cA + 32;
#pragma unroll
    for (int i = 0; i < 4; i++) {
        int r0 = rowBase + ty*8 + 2*i;
#pragma unroll
        for (int lane = 0; lane < 2; lane++) {
            int bt = r0 + lane;
            size_t baseA = (size_t)bt*ND + n*DD + cA;
            size_t baseB = (size_t)bt*ND + n*DD + cB;
            float4 x0 = *(const float4*)(g_Xp + baseA);
            float4 x1 = *(const float4*)(g_Xp + baseB);
            float v[8];
#pragma unroll
            for (int j = 0; j < 8; j++)
                v[j] = lane ? hi2(acc[i][j]) : lo2(acc[i][j]);
            float4 o0, o1;
            o0.x = gated(x0.x + v[0]); o0.y = gated(x0.y + v[1]);
            o0.z = gated(x0.z + v[2]); o0.w = gated(x0.w + v[3]);
            o1.x = gated(x1.x + v[4]); o1.y = gated(x1.y + v[5]);
            o1.z = gated(x1.z + v[6]); o1.w = gated(x1.w + v[7]);
            *(float4*)(Hout + baseA) = o0;
            *(float4*)(Hout + baseB) = o1;
        }
    }
}

// ---------------- output: [Xp|H1|H2] @ gcnW^T + gcnB -> [B,D,N,T] ----------------
__global__ void __launch_bounds__(128) k_out(const float* __restrict__ gcnB,
                                             float* __restrict__ out) {
    const int b = blockIdx.y;
    const int nBase = blockIdx.x*4;
    __shared__ __align__(16) float Hc[4*12*192];
    const int tid = threadIdx.x;
    float4* Hc4 = (float4*)Hc;
#pragma unroll
    for (int i = 0; i < 18; i++) {
        int lin4 = tid + i*128;
        int nl = lin4 / 576;
        int rem = lin4 - nl*576;
        int t = rem / 48;
        int f4 = rem - t*48;
        int seg = f4 >> 4, fd4 = f4 & 15;
        const float* src = (seg == 0) ? g_Xp : ((seg == 1) ? g_H1 : g_H2);
        Hc4[lin4] = *(const float4*)(src + (size_t)(b*TT+t)*ND + (nBase+nl)*DD + fd4*4);
    }
    __syncthreads();
    const int d2 = tid & 31, nloc = tid >> 5;
    u64 acc[12][2] = {};
    const ulonglong2* WT = (const ulonglong2*)g_gcnWT4;
#pragma unroll 4
    for (int f4 = 0; f4 < 48; f4++) {
        ulonglong2 wA = WT[f4*64 + d2];
        ulonglong2 wB = WT[f4*64 + d2 + 32];
        const float* hb = &Hc[nloc*2304 + f4*4];
#pragma unroll
        for (int t = 0; t < 12; t++) {
            ulonglong2 hp = *(const ulonglong2*)&hb[t*192];
            fma2(acc[t][0], hp.x, wA.x);
            fma2(acc[t][0], hp.y, wA.y);
            fma2(acc[t][1], hp.x, wB.x);
            fma2(acc[t][1], hp.y, wB.y);
        }
    }
    const int n = nBase + nloc;
#pragma unroll
    for (int dsel = 0; dsel < 2; dsel++) {
        int d = d2 + dsel*32;
        float bias = gcnB[d];
        float* op = out + ((size_t)(b*DD+d)*NN + n)*TT;
        float v[12];
#pragma unroll
        for (int t = 0; t < 12; t++) v[t] = lo2(acc[t][dsel]) + hi2(acc[t][dsel]) + bias;
#pragma unroll
        for (int q = 0; q < 3; q++)
            *(float4*)&op[q*4] = make_float4(v[q*4], v[q*4+1], v[q*4+2], v[q*4+3]);
    }
}

// ---------------- launcher (k_adj stays in the ncu capture slot #4) --------
extern "C" void kernel_launch(void* const* d_in, const int* in_sizes, int n_in,
                              void* d_out, int out_size) {
    const float* X    = (const float*)d_in[0];
    const float* te   = (const float*)d_in[1];
    const float* adjW = (const float*)d_in[2];
    const float* adjB = (const float*)d_in[3];
    const float* tW1  = (const float*)d_in[4];
    const float* tW2  = (const float*)d_in[5];
    const float* a1   = (const float*)d_in[6];
    const float* a2   = (const float*)d_in[7];
    const float* b1   = (const float*)d_in[8];
    const float* b2   = (const float*)d_in[9];
    const float* gcnW = (const float*)d_in[10];
    const float* gcnB = (const float*)d_in[11];
    float* out = (float*)d_out;

    k_SB <<<(NN2 + 255)/256, 256>>>(a1, a2, b1, b2);          // 1
    k_txp<<<dim3(NN, BB), 256>>>(X);                          // 2
    k_Wp <<<(NN*DD*DD + 255)/256, 256>>>(tW1, tW2);           // 3
    k_adj<<<dim3(4500), 128>>>(te, adjW, adjB);               // 4  <- capture slot

    // hop 1
    k_mm    <<<dim3(3, BT), 128>>>(0);                        // 5
    k_nodemm<<<dim3(3, NN), 128>>>(0);                        // 6
    // hop 2
    k_mm    <<<dim3(3, BT), 128>>>(1);                        // 7
    k_nodemm<<<dim3(3, NN), 128>>>(1);                        // 8

    k_gWT<<<(192*DD + 255)/256, 256>>>(gcnW);                 // 9
    k_out<<<dim3(75, BB), 128>>>(gcnB, out);                  // 10
}